// round 2
// baseline (speedup 1.0000x reference)
#include <cuda_runtime.h>
#include <math.h>

// Fixed problem geometry (from reference): T=1e6, D=82, NUM_GROUPS=256
#define D        82
#define NGROUP   256
#define NSTAT    6          // count, Sx, Sy, Sxx, Syy, Sxy
#define TPB      256

// Global scratch for group statistics: [NSTAT][NGROUP] doubles
__device__ double g_stats[NSTAT * NGROUP];

__global__ void zero_stats_kernel() {
    int i = blockIdx.x * blockDim.x + threadIdx.x;
    if (i < NSTAT * NGROUP) g_stats[i] = 0.0;
}

// Kernel 1: pred[t] = sqrt(sum_d (X1-X2)^2 * W[d]); fused single-pass group stats
__global__ __launch_bounds__(TPB)
void pred_stats_kernel(const float* __restrict__ X1,
                       const float* __restrict__ X2,
                       const float* __restrict__ Y,
                       const float* __restrict__ W,
                       const int*   __restrict__ mask,
                       float* __restrict__ pred_out,   // may be null
                       int T)
{
    __shared__ float  sW[D];
    __shared__ double sStat[NSTAT * NGROUP];   // 12 KB

    for (int i = threadIdx.x; i < NSTAT * NGROUP; i += TPB) sStat[i] = 0.0;
    if (threadIdx.x < D) sW[threadIdx.x] = W[threadIdx.x];
    __syncthreads();

    int t = blockIdx.x * TPB + threadIdx.x;
    if (t < T) {
        // Row base: t*82 floats = t*328 bytes -> always 8-byte aligned (float2 OK)
        const float2* __restrict__ a = (const float2*)(X1 + (size_t)t * D);
        const float2* __restrict__ b = (const float2*)(X2 + (size_t)t * D);

        float s = 0.0f;
        #pragma unroll
        for (int i = 0; i < D / 2; i++) {       // 41 float2 pairs
            float2 u = a[i];
            float2 v = b[i];
            float d0 = u.x - v.x;
            float d1 = u.y - v.y;
            s = fmaf(d0 * d0, sW[2 * i],     s);
            s = fmaf(d1 * d1, sW[2 * i + 1], s);
        }
        float x = sqrtf(s);
        if (pred_out) pred_out[t] = x;

        float y = Y[t];
        int   g = mask[t];
        double dx = (double)x, dy = (double)y;
        atomicAdd(&sStat[0 * NGROUP + g], 1.0);
        atomicAdd(&sStat[1 * NGROUP + g], dx);
        atomicAdd(&sStat[2 * NGROUP + g], dy);
        atomicAdd(&sStat[3 * NGROUP + g], dx * dx);
        atomicAdd(&sStat[4 * NGROUP + g], dy * dy);
        atomicAdd(&sStat[5 * NGROUP + g], dx * dy);
    }
    __syncthreads();

    // Flush block partials to global (distinct addresses -> cheap L2 atomics)
    for (int i = threadIdx.x; i < NSTAT * NGROUP; i += TPB) {
        double v = sStat[i];
        if (v != 0.0) atomicAdd(&g_stats[i], v);
    }
}

// Kernel 2: per-group Pearson |r|, mean over groups -> coeff
__global__ __launch_bounds__(NGROUP)
void finalize_kernel(float* __restrict__ coeff_out)
{
    __shared__ double red[NGROUP];
    int g = threadIdx.x;

    double n   = g_stats[0 * NGROUP + g];
    double Sx  = g_stats[1 * NGROUP + g];
    double Sy  = g_stats[2 * NGROUP + g];
    double Sxx = g_stats[3 * NGROUP + g];
    double Syy = g_stats[4 * NGROUP + g];
    double Sxy = g_stats[5 * NGROUP + g];

    double nom = Sxy - Sx * Sy / n;
    double dx  = Sxx - Sx * Sx / n;
    double dy  = Syy - Sy * Sy / n;
    double r   = fabs(nom / sqrt(dx * dy));

    red[g] = r;
    __syncthreads();
    #pragma unroll
    for (int ofs = NGROUP / 2; ofs > 0; ofs >>= 1) {
        if (g < ofs) red[g] += red[g + ofs];
        __syncthreads();
    }
    if (g == 0 && coeff_out) coeff_out[0] = (float)(red[0] / (double)NGROUP);
}

extern "C" void kernel_launch(void* const* d_in, const int* in_sizes, int n_in,
                              void* d_out, int out_size)
{
    const float* X1   = (const float*)d_in[0];
    const float* X2   = (const float*)d_in[1];
    const float* Y    = (const float*)d_in[2];
    const float* W    = (const float*)d_in[3];
    const int*   mask = (const int*)  d_in[4];

    int T = in_sizes[0] / D;

    float* out = (float*)d_out;
    float* coeff_out = nullptr;
    float* pred_out  = nullptr;
    if (out_size == T + 1) {            // (coeff, pred) flattened in return order
        coeff_out = out;
        pred_out  = out + 1;
    } else if (out_size == T) {         // pred only
        pred_out  = out;
    } else {                            // coeff only (or unknown small)
        coeff_out = out;
    }

    zero_stats_kernel<<<(NSTAT * NGROUP + 255) / 256, 256>>>();

    int blocks = (T + TPB - 1) / TPB;
    pred_stats_kernel<<<blocks, TPB>>>(X1, X2, Y, W, mask, pred_out, T);

    finalize_kernel<<<1, NGROUP>>>(coeff_out);
}

// round 3
// speedup vs baseline: 1.3422x; 1.3422x over previous
#include <cuda_runtime.h>
#include <math.h>

// Problem geometry (fixed by reference): T=1e6, D=82, 256 groups
#define D        82
#define NGROUP   256
#define NSTAT    6            // count, Sx, Sy, Sxx, Syy, Sxy
#define TPB      96           // threads per block == rows per tile
#define ROWS     96
#define TILE_ELEMS (ROWS * D)        // 7872 floats
#define TILE_V4    (TILE_ELEMS / 4)  // 1968 float4 (ROWS*D divisible by 4)
#define MAX_GRID   740               // 148 SMs x 5 blocks (smem-limited)

// Global scratch for group statistics: [NSTAT][NGROUP] doubles
__device__ double g_stats[NSTAT * NGROUP];

__global__ void zero_stats_kernel() {
    int i = blockIdx.x * blockDim.x + threadIdx.x;
    if (i < NSTAT * NGROUP) g_stats[i] = 0.0;
}

// Persistent kernel: coalesced float4 streaming -> shared staging of (X1-X2)^2,
// then per-thread row dot with W, sqrt, fused single-pass group stats.
__global__ __launch_bounds__(TPB)
void pred_stats_kernel(const float4* __restrict__ X1,
                       const float4* __restrict__ X2,
                       const float*  __restrict__ Y,
                       const float*  __restrict__ W,
                       const int*    __restrict__ mask,
                       float* __restrict__ pred_out,   // may be null
                       int T, int numTiles)
{
    __shared__ __align__(16) float sDiff[TILE_ELEMS];  // 31.5 KB: squared diffs
    __shared__ double sStat[NSTAT * NGROUP];           // 12.3 KB
    __shared__ float  sW[D];

    const int tid = threadIdx.x;

    for (int i = tid; i < NSTAT * NGROUP; i += TPB) sStat[i] = 0.0;
    if (tid < D) sW[tid] = W[tid];
    // first-iteration __syncthreads below covers this init

    for (int tile = blockIdx.x; tile < numTiles; tile += gridDim.x) {
        const int row0 = tile * ROWS;
        const int rows = min(ROWS, T - row0);
        const int n4   = (rows * D) / 4;          // rows always even -> divisible
        const size_t base4 = (size_t)row0 * D / 4; // tile base is float4-aligned

        __syncthreads();   // prior phase-2 reads done before overwrite (and init)

        // Phase 1: fully coalesced float4 stream; store d^2 to shared
        #pragma unroll 4
        for (int i = tid; i < n4; i += TPB) {
            float4 a = X1[base4 + i];
            float4 b = X2[base4 + i];
            float4 d;
            d.x = a.x - b.x; d.x *= d.x;
            d.y = a.y - b.y; d.y *= d.y;
            d.z = a.z - b.z; d.z *= d.z;
            d.w = a.w - b.w; d.w *= d.w;
            reinterpret_cast<float4*>(sDiff)[i] = d;
        }
        __syncthreads();

        // Phase 2: one row per thread (shared reads, 2-way conflict max)
        if (tid < rows) {
            const int t = row0 + tid;
            const float2* __restrict__ dd =
                reinterpret_cast<const float2*>(sDiff + tid * D);  // 8B aligned
            float s = 0.0f;
            #pragma unroll
            for (int i = 0; i < D / 2; i++) {
                float2 v = dd[i];
                s = fmaf(v.x, sW[2 * i],     s);
                s = fmaf(v.y, sW[2 * i + 1], s);
            }
            float x = sqrtf(s);
            if (pred_out) pred_out[t] = x;

            float y = Y[t];
            int   g = mask[t];
            double dx = (double)x, dy = (double)y;
            atomicAdd(&sStat[0 * NGROUP + g], 1.0);
            atomicAdd(&sStat[1 * NGROUP + g], dx);
            atomicAdd(&sStat[2 * NGROUP + g], dy);
            atomicAdd(&sStat[3 * NGROUP + g], dx * dx);
            atomicAdd(&sStat[4 * NGROUP + g], dy * dy);
            atomicAdd(&sStat[5 * NGROUP + g], dx * dy);
        }
    }

    __syncthreads();
    // One flush per persistent block (distinct-address L2 double atomics)
    for (int i = tid; i < NSTAT * NGROUP; i += TPB) {
        double v = sStat[i];
        if (v != 0.0) atomicAdd(&g_stats[i], v);
    }
}

// Per-group Pearson |r|, mean over groups -> coeff
__global__ __launch_bounds__(NGROUP)
void finalize_kernel(float* __restrict__ coeff_out)
{
    __shared__ double red[NGROUP];
    int g = threadIdx.x;

    double n   = g_stats[0 * NGROUP + g];
    double Sx  = g_stats[1 * NGROUP + g];
    double Sy  = g_stats[2 * NGROUP + g];
    double Sxx = g_stats[3 * NGROUP + g];
    double Syy = g_stats[4 * NGROUP + g];
    double Sxy = g_stats[5 * NGROUP + g];

    double nom = Sxy - Sx * Sy / n;
    double dx  = Sxx - Sx * Sx / n;
    double dy  = Syy - Sy * Sy / n;
    double r   = fabs(nom / sqrt(dx * dy));

    red[g] = r;
    __syncthreads();
    #pragma unroll
    for (int ofs = NGROUP / 2; ofs > 0; ofs >>= 1) {
        if (g < ofs) red[g] += red[g + ofs];
        __syncthreads();
    }
    if (g == 0 && coeff_out) coeff_out[0] = (float)(red[0] / (double)NGROUP);
}

extern "C" void kernel_launch(void* const* d_in, const int* in_sizes, int n_in,
                              void* d_out, int out_size)
{
    const float* X1   = (const float*)d_in[0];
    const float* X2   = (const float*)d_in[1];
    const float* Y    = (const float*)d_in[2];
    const float* W    = (const float*)d_in[3];
    const int*   mask = (const int*)  d_in[4];

    int T = in_sizes[0] / D;

    float* out = (float*)d_out;
    float* coeff_out = nullptr;
    float* pred_out  = nullptr;
    if (out_size == T + 1) {            // (coeff, pred) flattened in return order
        coeff_out = out;
        pred_out  = out + 1;
    } else if (out_size == T) {         // pred only
        pred_out  = out;
    } else {                            // coeff only
        coeff_out = out;
    }

    zero_stats_kernel<<<(NSTAT * NGROUP + 255) / 256, 256>>>();

    int numTiles = (T + ROWS - 1) / ROWS;
    int grid = numTiles < MAX_GRID ? numTiles : MAX_GRID;
    pred_stats_kernel<<<grid, TPB>>>((const float4*)X1, (const float4*)X2,
                                     Y, W, mask, pred_out, T, numTiles);

    finalize_kernel<<<1, NGROUP>>>(coeff_out);
}

// round 4
// speedup vs baseline: 1.5871x; 1.1825x over previous
#include <cuda_runtime.h>
#include <math.h>

// Problem geometry (fixed by reference): T=1e6, D=82, 256 groups
#define D        82
#define NGROUP   256
#define NSTAT    6            // count, Sx, Sy, Sxx, Syy, Sxy
#define TPB      96           // threads per block == rows per tile
#define ROWS     96
#define TILE_ELEMS (ROWS * D)        // 7872 floats
#define TILE_V4    (TILE_ELEMS / 4)  // 1968 float4
#define FULL_ITERS (TILE_V4 / TPB)   // 20 (remainder handled by tail)
#define BLOCKS_PER_SM 6
#define MAX_GRID   (148 * BLOCKS_PER_SM)   // 888

// Global scratch for group statistics: [NSTAT][NGROUP] doubles
__device__ double g_stats[NSTAT * NGROUP];

__global__ void zero_stats_kernel() {
    int i = blockIdx.x * blockDim.x + threadIdx.x;
    if (i < NSTAT * NGROUP) g_stats[i] = 0.0;
}

// Persistent kernel: coalesced float4 streaming -> shared staging of (X1-X2)^2,
// per-thread row dot with W, sqrt, fused single-pass group stats.
// Stats accumulate in FLOAT shared atomics (per-block partials are sums of only
// ~5 values/group -> fp32 exact enough), promoted to double at the global flush.
__global__ __launch_bounds__(TPB, BLOCKS_PER_SM)
void pred_stats_kernel(const float4* __restrict__ X1,
                       const float4* __restrict__ X2,
                       const float*  __restrict__ Y,
                       const float*  __restrict__ W,
                       const int*    __restrict__ mask,
                       float* __restrict__ pred_out,   // may be null
                       int T, int numTiles)
{
    __shared__ __align__(16) float sDiff[TILE_ELEMS];  // 31.5 KB squared diffs
    __shared__ float sStat[NSTAT * NGROUP];            // 6 KB float partials
    __shared__ float sW[D];

    const int tid = threadIdx.x;

    for (int i = tid; i < NSTAT * NGROUP; i += TPB) sStat[i] = 0.0f;
    if (tid < D) sW[tid] = W[tid];
    // first-iteration __syncthreads below covers this init

    for (int tile = blockIdx.x; tile < numTiles; tile += gridDim.x) {
        const int row0 = tile * ROWS;
        const int rows = min(ROWS, T - row0);
        const int t    = row0 + tid;
        const size_t base4 = (size_t)row0 * D / 4;  // tile base float4-aligned

        __syncthreads();   // prior phase-2 reads done before overwrite (and init)

        // Prefetch this row's Y/mask during the streaming phase
        float yReg = 0.0f; int gReg = 0;
        if (tid < rows) { yReg = Y[t]; gReg = mask[t]; }

        const float4* __restrict__ A = X1 + base4;
        const float4* __restrict__ B = X2 + base4;
        float4* __restrict__ S4 = reinterpret_cast<float4*>(sDiff);

        if (rows == ROWS) {
            // Full tile: fixed trip count, fully unrolled -> batched LDG.128s
            int i = tid;
            #pragma unroll
            for (int k = 0; k < FULL_ITERS; k++, i += TPB) {
                float4 a = A[i];
                float4 b = B[i];
                float4 d;
                d.x = a.x - b.x; d.x *= d.x;
                d.y = a.y - b.y; d.y *= d.y;
                d.z = a.z - b.z; d.z *= d.z;
                d.w = a.w - b.w; d.w *= d.w;
                S4[i] = d;
            }
            if (i < TILE_V4) {                       // tail: 48 threads
                float4 a = A[i];
                float4 b = B[i];
                float4 d;
                d.x = a.x - b.x; d.x *= d.x;
                d.y = a.y - b.y; d.y *= d.y;
                d.z = a.z - b.z; d.z *= d.z;
                d.w = a.w - b.w; d.w *= d.w;
                S4[i] = d;
            }
        } else {
            const int n4 = (rows * D) / 4;           // rows even -> divisible
            for (int i = tid; i < n4; i += TPB) {
                float4 a = A[i];
                float4 b = B[i];
                float4 d;
                d.x = a.x - b.x; d.x *= d.x;
                d.y = a.y - b.y; d.y *= d.y;
                d.z = a.z - b.z; d.z *= d.z;
                d.w = a.w - b.w; d.w *= d.w;
                S4[i] = d;
            }
        }
        __syncthreads();

        // Phase 2: one row per thread (shared reads, 2-way conflict max)
        if (tid < rows) {
            const float2* __restrict__ dd =
                reinterpret_cast<const float2*>(sDiff + tid * D);  // 8B aligned
            float s = 0.0f;
            #pragma unroll
            for (int i = 0; i < D / 2; i++) {
                float2 v = dd[i];
                s = fmaf(v.x, sW[2 * i],     s);
                s = fmaf(v.y, sW[2 * i + 1], s);
            }
            float x = sqrtf(s);
            if (pred_out) pred_out[t] = x;

            const int g = gReg;
            const float y = yReg;
            atomicAdd(&sStat[0 * NGROUP + g], 1.0f);
            atomicAdd(&sStat[1 * NGROUP + g], x);
            atomicAdd(&sStat[2 * NGROUP + g], y);
            atomicAdd(&sStat[3 * NGROUP + g], x * x);
            atomicAdd(&sStat[4 * NGROUP + g], y * y);
            atomicAdd(&sStat[5 * NGROUP + g], x * y);
        }
    }

    __syncthreads();
    // One flush per persistent block: promote float partials to global doubles
    for (int i = tid; i < NSTAT * NGROUP; i += TPB) {
        float v = sStat[i];
        if (v != 0.0f) atomicAdd(&g_stats[i], (double)v);
    }
}

// Per-group Pearson |r|, mean over groups -> coeff
__global__ __launch_bounds__(NGROUP)
void finalize_kernel(float* __restrict__ coeff_out)
{
    __shared__ double red[NGROUP];
    int g = threadIdx.x;

    double n   = g_stats[0 * NGROUP + g];
    double Sx  = g_stats[1 * NGROUP + g];
    double Sy  = g_stats[2 * NGROUP + g];
    double Sxx = g_stats[3 * NGROUP + g];
    double Syy = g_stats[4 * NGROUP + g];
    double Sxy = g_stats[5 * NGROUP + g];

    double nom = Sxy - Sx * Sy / n;
    double dx  = Sxx - Sx * Sx / n;
    double dy  = Syy - Sy * Sy / n;
    double r   = fabs(nom / sqrt(dx * dy));

    red[g] = r;
    __syncthreads();
    #pragma unroll
    for (int ofs = NGROUP / 2; ofs > 0; ofs >>= 1) {
        if (g < ofs) red[g] += red[g + ofs];
        __syncthreads();
    }
    if (g == 0 && coeff_out) coeff_out[0] = (float)(red[0] / (double)NGROUP);
}

extern "C" void kernel_launch(void* const* d_in, const int* in_sizes, int n_in,
                              void* d_out, int out_size)
{
    const float* X1   = (const float*)d_in[0];
    const float* X2   = (const float*)d_in[1];
    const float* Y    = (const float*)d_in[2];
    const float* W    = (const float*)d_in[3];
    const int*   mask = (const int*)  d_in[4];

    int T = in_sizes[0] / D;

    float* out = (float*)d_out;
    float* coeff_out = nullptr;
    float* pred_out  = nullptr;
    if (out_size == T + 1) {            // (coeff, pred) flattened in return order
        coeff_out = out;
        pred_out  = out + 1;
    } else if (out_size == T) {         // pred only
        pred_out  = out;
    } else {                            // coeff only
        coeff_out = out;
    }

    zero_stats_kernel<<<(NSTAT * NGROUP + 255) / 256, 256>>>();

    int numTiles = (T + ROWS - 1) / ROWS;
    int grid = numTiles < MAX_GRID ? numTiles : MAX_GRID;
    pred_stats_kernel<<<grid, TPB>>>((const float4*)X1, (const float4*)X2,
                                     Y, W, mask, pred_out, T, numTiles);

    finalize_kernel<<<1, NGROUP>>>(coeff_out);
}